// round 3
// baseline (speedup 1.0000x reference)
#include <cuda_runtime.h>
#include <math.h>

#define HIDDEN 1024
#define SEQ    4096
#define BATCH  2
#define HEADS  16
#define HDIM   64
#define M_TOT  (BATCH*SEQ)           // 8192
#define QKV_O  (3*HIDDEN)            // 3072

// Scratch (device globals -> BSS, no allocation)
__device__ float g_q [(size_t)BATCH*HEADS*SEQ*HDIM];   // 32MB
__device__ float g_k [(size_t)BATCH*HEADS*SEQ*HDIM];
__device__ float g_v [(size_t)BATCH*HEADS*SEQ*HDIM];
__device__ float g_ao[(size_t)M_TOT*HIDDEN];           // attention output in [B,N,C]

// ---------------------------------------------------------------------------
// GEMM 1: qkv = x @ qkv_w^T + qkv_b, scattered into g_q/g_k/g_v as [B,H,N,D]
// A: x [8192,1024] row-major, B: qkv_w [3072,1024] row-major (TN gemm)
// Tile 128x128x16, 256 threads, 8x8 per thread.
// ---------------------------------------------------------------------------
__global__ __launch_bounds__(256) void qkv_gemm(const float* __restrict__ X,
                                                const float* __restrict__ W,
                                                const float* __restrict__ Bi)
{
    __shared__ float As[16][132];
    __shared__ float Bs[16][132];

    const int m0 = blockIdx.y * 128;
    const int o0 = blockIdx.x * 128;
    const int tid = threadIdx.x;
    const int tx = tid & 15, ty = tid >> 4;

    float acc[8][8];
#pragma unroll
    for (int i = 0; i < 8; i++)
#pragma unroll
        for (int j = 0; j < 8; j++) acc[i][j] = 0.f;

    for (int k0 = 0; k0 < HIDDEN; k0 += 16) {
#pragma unroll
        for (int l = 0; l < 2; l++) {
            int i = tid + l * 256;           // float4 index 0..511
            int r = i >> 2;                  // row 0..127
            int c = (i & 3) * 4;             // k col 0..12
            float4 t = *(const float4*)(X + (size_t)(m0 + r) * HIDDEN + k0 + c);
            As[c][r] = t.x; As[c+1][r] = t.y; As[c+2][r] = t.z; As[c+3][r] = t.w;
            float4 u = *(const float4*)(W + (size_t)(o0 + r) * HIDDEN + k0 + c);
            Bs[c][r] = u.x; Bs[c+1][r] = u.y; Bs[c+2][r] = u.z; Bs[c+3][r] = u.w;
        }
        __syncthreads();

#pragma unroll
        for (int kk = 0; kk < 16; kk++) {
            float a[8], b[8];
            const float4* ap = (const float4*)&As[kk][ty * 8];
            const float4* bp = (const float4*)&Bs[kk][tx * 8];
            float4 a0 = ap[0], a1 = ap[1];
            float4 b0 = bp[0], b1 = bp[1];
            a[0]=a0.x; a[1]=a0.y; a[2]=a0.z; a[3]=a0.w;
            a[4]=a1.x; a[5]=a1.y; a[6]=a1.z; a[7]=a1.w;
            b[0]=b0.x; b[1]=b0.y; b[2]=b0.z; b[3]=b0.w;
            b[4]=b1.x; b[5]=b1.y; b[6]=b1.z; b[7]=b1.w;
#pragma unroll
            for (int i = 0; i < 8; i++)
#pragma unroll
                for (int j = 0; j < 8; j++) acc[i][j] += a[i] * b[j];
        }
        __syncthreads();
    }

    // Epilogue: add bias, scatter into q/k/v [B,H,N,D]
#pragma unroll
    for (int j = 0; j < 8; j++) {
        int o = o0 + tx * 8 + j;
        float bias = Bi[o];
        int which = o >> 10;          // 0=q,1=k,2=v
        int c = o & 1023;
        int h = c >> 6;
        int d = c & 63;
        float* dst = (which == 0) ? g_q : ((which == 1) ? g_k : g_v);
#pragma unroll
        for (int i = 0; i < 8; i++) {
            int m = m0 + ty * 8 + i;
            int bb = m >> 12;         // m / 4096
            int n  = m & 4095;
            dst[(((size_t)(bb * HEADS + h)) * SEQ + n) * HDIM + d] = acc[i][j] + bias;
        }
    }
}

// ---------------------------------------------------------------------------
// Flash attention fp32. One block per (bh, q-tile of 64). 256 threads.
// Key tile = 32. Online softmax. Writes g_ao in [B,N,C] layout.
// ---------------------------------------------------------------------------
__global__ __launch_bounds__(256) void flash_attn()
{
    __shared__ float Qs[64][65];
    __shared__ float Ks[32][65];
    __shared__ float Vs[32][65];
    __shared__ float Ss[64][33];
    __shared__ float mst[64], lst[64], rsc[64];

    const int bh = blockIdx.y;                 // 0..31
    const int qt = blockIdx.x;                 // 0..63
    const int tid = threadIdx.x;
    const int tx = tid & 15, ty = tid >> 4;
    const float scale = 0.125f;                // 1/sqrt(64)

    const float* qb = g_q + ((size_t)bh * SEQ + qt * 64) * HDIM;
    const float* kb = g_k + (size_t)bh * SEQ * HDIM;
    const float* vb = g_v + (size_t)bh * SEQ * HDIM;

    // Load Q tile (64x64), pre-scale
#pragma unroll
    for (int l = 0; l < 4; l++) {
        int i = tid + l * 256;                 // 1024 float4s
        int r = i >> 4, c = (i & 15) << 2;
        float4 t = *(const float4*)(qb + r * HDIM + c);
        Qs[r][c] = t.x * scale; Qs[r][c+1] = t.y * scale;
        Qs[r][c+2] = t.z * scale; Qs[r][c+3] = t.w * scale;
    }
    if (tid < 64) { mst[tid] = -1e30f; lst[tid] = 0.f; }

    float acc[4][4];
#pragma unroll
    for (int i = 0; i < 4; i++)
#pragma unroll
        for (int j = 0; j < 4; j++) acc[i][j] = 0.f;

    for (int kt = 0; kt < SEQ; kt += 32) {
        // Load K,V tiles (32x64 each)
#pragma unroll
        for (int l = 0; l < 2; l++) {
            int i = tid + l * 256;             // 512 float4s
            int r = i >> 4, c = (i & 15) << 2;
            float4 t = *(const float4*)(kb + (size_t)(kt + r) * HDIM + c);
            Ks[r][c] = t.x; Ks[r][c+1] = t.y; Ks[r][c+2] = t.z; Ks[r][c+3] = t.w;
            float4 u = *(const float4*)(vb + (size_t)(kt + r) * HDIM + c);
            Vs[r][c] = u.x; Vs[r][c+1] = u.y; Vs[r][c+2] = u.z; Vs[r][c+3] = u.w;
        }
        __syncthreads();

        // S = Qs @ Ks^T : each thread 4q x 2k
        float s[4][2];
#pragma unroll
        for (int i = 0; i < 4; i++) { s[i][0] = 0.f; s[i][1] = 0.f; }
#pragma unroll 8
        for (int d = 0; d < 64; d++) {
            float b0 = Ks[tx * 2][d];
            float b1 = Ks[tx * 2 + 1][d];
#pragma unroll
            for (int i = 0; i < 4; i++) {
                float a = Qs[ty * 4 + i][d];
                s[i][0] += a * b0;
                s[i][1] += a * b1;
            }
        }
#pragma unroll
        for (int i = 0; i < 4; i++) {
            Ss[ty * 4 + i][tx * 2]     = s[i][0];
            Ss[ty * 4 + i][tx * 2 + 1] = s[i][1];
        }
        __syncthreads();

        // Online softmax: warp w handles rows w*8..w*8+7, 32 cols = 1/lane
        {
            int w = tid >> 5, lane = tid & 31;
#pragma unroll
            for (int rr = 0; rr < 8; rr++) {
                int r = w * 8 + rr;
                float v = Ss[r][lane];
                float mx = v;
#pragma unroll
                for (int off = 16; off > 0; off >>= 1)
                    mx = fmaxf(mx, __shfl_xor_sync(0xffffffffu, mx, off));
                float mo = mst[r];
                float mn = fmaxf(mo, mx);
                float p = __expf(v - mn);
                Ss[r][lane] = p;
                float sum = p;
#pragma unroll
                for (int off = 16; off > 0; off >>= 1)
                    sum += __shfl_xor_sync(0xffffffffu, sum, off);
                float scl = __expf(mo - mn);
                if (lane == 0) {
                    mst[r] = mn;
                    lst[r] = lst[r] * scl + sum;
                    rsc[r] = scl;
                }
            }
        }
        __syncthreads();

        // O = O*rsc + P @ V : each thread 4q x 4d
#pragma unroll
        for (int i = 0; i < 4; i++) {
            float scl = rsc[ty * 4 + i];
#pragma unroll
            for (int j = 0; j < 4; j++) acc[i][j] *= scl;
        }
#pragma unroll 8
        for (int k2 = 0; k2 < 32; k2++) {
            float v0 = Vs[k2][tx * 4];
            float v1 = Vs[k2][tx * 4 + 1];
            float v2 = Vs[k2][tx * 4 + 2];
            float v3 = Vs[k2][tx * 4 + 3];
#pragma unroll
            for (int i = 0; i < 4; i++) {
                float p = Ss[ty * 4 + i][k2];
                acc[i][0] += p * v0;
                acc[i][1] += p * v1;
                acc[i][2] += p * v2;
                acc[i][3] += p * v3;
            }
        }
        __syncthreads();
    }

    // Write out: [B,N,C] with C index = h*64 + d
    const int b = bh >> 4, h = bh & 15;
#pragma unroll
    for (int i = 0; i < 4; i++) {
        int r = ty * 4 + i;
        int n = qt * 64 + r;
        float inv = 1.f / lst[r];
#pragma unroll
        for (int j = 0; j < 4; j++) {
            g_ao[((size_t)b * SEQ + n) * HIDDEN + h * 64 + tx * 4 + j] = acc[i][j] * inv;
        }
    }
}

// ---------------------------------------------------------------------------
// GEMM 2: out = g_ao @ out_w^T + out_b  ->  d_out [8192,1024]
// ---------------------------------------------------------------------------
__global__ __launch_bounds__(256) void out_gemm(const float* __restrict__ W,
                                                const float* __restrict__ Bi,
                                                float* __restrict__ Out)
{
    __shared__ float As[16][132];
    __shared__ float Bs[16][132];

    const int m0 = blockIdx.y * 128;
    const int o0 = blockIdx.x * 128;
    const int tid = threadIdx.x;
    const int tx = tid & 15, ty = tid >> 4;

    float acc[8][8];
#pragma unroll
    for (int i = 0; i < 8; i++)
#pragma unroll
        for (int j = 0; j < 8; j++) acc[i][j] = 0.f;

    for (int k0 = 0; k0 < HIDDEN; k0 += 16) {
#pragma unroll
        for (int l = 0; l < 2; l++) {
            int i = tid + l * 256;
            int r = i >> 2;
            int c = (i & 3) * 4;
            float4 t = *(const float4*)(g_ao + (size_t)(m0 + r) * HIDDEN + k0 + c);
            As[c][r] = t.x; As[c+1][r] = t.y; As[c+2][r] = t.z; As[c+3][r] = t.w;
            float4 u = *(const float4*)(W + (size_t)(o0 + r) * HIDDEN + k0 + c);
            Bs[c][r] = u.x; Bs[c+1][r] = u.y; Bs[c+2][r] = u.z; Bs[c+3][r] = u.w;
        }
        __syncthreads();

#pragma unroll
        for (int kk = 0; kk < 16; kk++) {
            float a[8], b[8];
            const float4* ap = (const float4*)&As[kk][ty * 8];
            const float4* bp = (const float4*)&Bs[kk][tx * 8];
            float4 a0 = ap[0], a1 = ap[1];
            float4 b0 = bp[0], b1 = bp[1];
            a[0]=a0.x; a[1]=a0.y; a[2]=a0.z; a[3]=a0.w;
            a[4]=a1.x; a[5]=a1.y; a[6]=a1.z; a[7]=a1.w;
            b[0]=b0.x; b[1]=b0.y; b[2]=b0.z; b[3]=b0.w;
            b[4]=b1.x; b[5]=b1.y; b[6]=b1.z; b[7]=b1.w;
#pragma unroll
            for (int i = 0; i < 8; i++)
#pragma unroll
                for (int j = 0; j < 8; j++) acc[i][j] += a[i] * b[j];
        }
        __syncthreads();
    }

#pragma unroll
    for (int j = 0; j < 8; j++) {
        int o = o0 + tx * 8 + j;
        float bias = Bi[o];
#pragma unroll
        for (int i = 0; i < 8; i++) {
            int m = m0 + ty * 8 + i;
            Out[(size_t)m * HIDDEN + o] = acc[i][j] + bias;
        }
    }
}

// ---------------------------------------------------------------------------
extern "C" void kernel_launch(void* const* d_in, const int* in_sizes, int n_in,
                              void* d_out, int out_size)
{
    const float* x     = (const float*)d_in[0];
    const float* qkv_w = (const float*)d_in[1];
    const float* qkv_b = (const float*)d_in[2];
    const float* out_w = (const float*)d_in[3];
    const float* out_b = (const float*)d_in[4];
    float* out = (float*)d_out;

    qkv_gemm<<<dim3(QKV_O / 128, M_TOT / 128), 256>>>(x, qkv_w, qkv_b);
    flash_attn<<<dim3(SEQ / 64, BATCH * HEADS), 256>>>();
    out_gemm<<<dim3(HIDDEN / 128, M_TOT / 128), 256>>>(out_w, out_b, out);
}

// round 4
// speedup vs baseline: 3.6072x; 3.6072x over previous
#include <cuda_runtime.h>
#include <math.h>

#define HIDDEN 1024
#define SEQ    4096
#define BATCH  2
#define HEADS  16
#define HDIM   64
#define M_TOT  (BATCH*SEQ)           // 8192
#define QKV_O  (3*HIDDEN)            // 3072

// Scratch (device globals -> BSS, no allocation)
__device__ float g_q [(size_t)BATCH*HEADS*SEQ*HDIM];
__device__ float g_k [(size_t)BATCH*HEADS*SEQ*HDIM];
__device__ float g_v [(size_t)BATCH*HEADS*SEQ*HDIM];
__device__ float g_ao[(size_t)M_TOT*HIDDEN];

// ---------------------------------------------------------------------------
// tf32 helpers
// ---------------------------------------------------------------------------
__device__ __forceinline__ unsigned f2tf32(float f) {
    unsigned r;
    asm("cvt.rna.tf32.f32 %0, %1;" : "=r"(r) : "f"(f));
    return r;
}

__device__ __forceinline__ void mma_tf32(float* c, unsigned a0, unsigned a1,
                                         unsigned a2, unsigned a3,
                                         unsigned b0, unsigned b1) {
    asm volatile(
        "mma.sync.aligned.m16n8k8.row.col.f32.tf32.tf32.f32 "
        "{%0,%1,%2,%3}, {%4,%5,%6,%7}, {%8,%9}, {%0,%1,%2,%3};"
        : "+f"(c[0]), "+f"(c[1]), "+f"(c[2]), "+f"(c[3])
        : "r"(a0), "r"(a1), "r"(a2), "r"(a3), "r"(b0), "r"(b1));
}

// ---------------------------------------------------------------------------
// Generic tf32 128x128x16 GEMM core pieces (used by both projection kernels)
// smem layout [k][m] / [k][n], pad 136 words -> conflict-free fragment loads.
// 256 threads = 8 warps, warp grid 4(m) x 2(n), warp tile 32x64.
// ---------------------------------------------------------------------------
#define GPAD 136

// ---------------------------------------------------------------------------
// GEMM 1: qkv = x @ qkv_w^T + qkv_b, scattered into g_q/g_k/g_v as [B,H,N,D]
// ---------------------------------------------------------------------------
__global__ __launch_bounds__(256) void qkv_gemm_tf32(const float* __restrict__ X,
                                                     const float* __restrict__ W,
                                                     const float* __restrict__ Bi)
{
    __shared__ unsigned As[16][GPAD];
    __shared__ unsigned Bs[16][GPAD];

    const int m0 = blockIdx.y * 128;
    const int o0 = blockIdx.x * 128;
    const int tid  = threadIdx.x;
    const int wid  = tid >> 5;
    const int lane = tid & 31;
    const int gid  = lane >> 2;     // groupID 0..7
    const int tg   = lane & 3;      // thread-in-group 0..3
    const int warp_m = wid >> 1;    // 0..3
    const int warp_n = wid & 1;     // 0..1

    float acc[2][8][4];
#pragma unroll
    for (int i = 0; i < 2; i++)
#pragma unroll
        for (int j = 0; j < 8; j++)
#pragma unroll
            for (int r = 0; r < 4; r++) acc[i][j][r] = 0.f;

    for (int k0 = 0; k0 < HIDDEN; k0 += 16) {
#pragma unroll
        for (int l = 0; l < 2; l++) {
            int i = tid + l * 256;          // 0..511
            int r = i >> 2;                 // 0..127
            int c = (i & 3) * 4;            // 0,4,8,12
            float4 t = *(const float4*)(X + (size_t)(m0 + r) * HIDDEN + k0 + c);
            As[c][r] = f2tf32(t.x); As[c+1][r] = f2tf32(t.y);
            As[c+2][r] = f2tf32(t.z); As[c+3][r] = f2tf32(t.w);
            float4 u = *(const float4*)(W + (size_t)(o0 + r) * HIDDEN + k0 + c);
            Bs[c][r] = f2tf32(u.x); Bs[c+1][r] = f2tf32(u.y);
            Bs[c+2][r] = f2tf32(u.z); Bs[c+3][r] = f2tf32(u.w);
        }
        __syncthreads();

#pragma unroll
        for (int ks = 0; ks < 2; ks++) {
            const int kk = ks * 8;
            unsigned a[2][4];
#pragma unroll
            for (int i = 0; i < 2; i++) {
                int rb = warp_m * 32 + i * 16 + gid;
                a[i][0] = As[kk + tg][rb];
                a[i][1] = As[kk + tg][rb + 8];
                a[i][2] = As[kk + tg + 4][rb];
                a[i][3] = As[kk + tg + 4][rb + 8];
            }
#pragma unroll
            for (int j = 0; j < 8; j++) {
                int cb = warp_n * 64 + j * 8 + gid;
                unsigned b0 = Bs[kk + tg][cb];
                unsigned b1 = Bs[kk + tg + 4][cb];
                mma_tf32(acc[0][j], a[0][0], a[0][1], a[0][2], a[0][3], b0, b1);
                mma_tf32(acc[1][j], a[1][0], a[1][1], a[1][2], a[1][3], b0, b1);
            }
        }
        __syncthreads();
    }

    // Epilogue: bias + scatter into q/k/v [B,H,N,D]
#pragma unroll
    for (int j = 0; j < 8; j++) {
#pragma unroll
        for (int cc = 0; cc < 2; cc++) {
            int o = o0 + warp_n * 64 + j * 8 + 2 * tg + cc;
            float bias = Bi[o];
            int which = o >> 10;
            int c = o & 1023;
            int h = c >> 6;
            int d = c & 63;
            float* dst = (which == 0) ? g_q : ((which == 1) ? g_k : g_v);
#pragma unroll
            for (int i = 0; i < 2; i++) {
#pragma unroll
                for (int rr = 0; rr < 2; rr++) {
                    int m = m0 + warp_m * 32 + i * 16 + gid + rr * 8;
                    int bb = m >> 12;
                    int n  = m & 4095;
                    dst[(((size_t)(bb * HEADS + h)) * SEQ + n) * HDIM + d] =
                        acc[i][j][rr * 2 + cc] + bias;
                }
            }
        }
    }
}

// ---------------------------------------------------------------------------
// Flash attention, tf32 MMA. One block per (bh, q-tile of 64). 128 threads.
// KV tile 64. Online softmax in registers. Writes g_ao in [B,N,C] layout.
// Dynamic smem: Qs[64][68] Ks[64][68] Vs[64][72] Ps[64][68] (uint32 tf32)
// ---------------------------------------------------------------------------
#define QPAD 68
#define VPAD 72
#define SM_Q  0
#define SM_K  (64*QPAD)
#define SM_V  (SM_K + 64*QPAD)
#define SM_P  (SM_V + 64*VPAD)
#define SM_WORDS (SM_P + 64*QPAD)   // 17664 words = 70656 bytes

__global__ __launch_bounds__(128) void flash_attn_tf32()
{
    extern __shared__ unsigned sm[];
    unsigned* Qs = sm + SM_Q;
    unsigned* Ks = sm + SM_K;
    unsigned* Vs = sm + SM_V;
    unsigned* Ps = sm + SM_P;

    const int bh = blockIdx.y;                 // 0..31
    const int qt = blockIdx.x;                 // 0..63
    const int tid  = threadIdx.x;
    const int wid  = tid >> 5;                 // 0..3
    const int lane = tid & 31;
    const int gid  = lane >> 2;
    const int tg   = lane & 3;
    const float scale = 0.125f;

    const float* qb = g_q + ((size_t)bh * SEQ + qt * 64) * HDIM;
    const float* kb = g_k + (size_t)bh * SEQ * HDIM;
    const float* vb = g_v + (size_t)bh * SEQ * HDIM;

    // Load + prescale Q tile (64x64)
#pragma unroll
    for (int l = 0; l < 8; l++) {
        int i = tid + l * 128;
        int r = i >> 4, c = (i & 15) << 2;
        float4 t = *(const float4*)(qb + r * HDIM + c);
        Qs[r * QPAD + c]     = f2tf32(t.x * scale);
        Qs[r * QPAD + c + 1] = f2tf32(t.y * scale);
        Qs[r * QPAD + c + 2] = f2tf32(t.z * scale);
        Qs[r * QPAD + c + 3] = f2tf32(t.w * scale);
    }

    const int rowbase = wid * 16;
    float oacc[8][4];
#pragma unroll
    for (int j = 0; j < 8; j++)
#pragma unroll
        for (int r = 0; r < 4; r++) oacc[j][r] = 0.f;
    float mrun0 = -1e30f, mrun1 = -1e30f;
    float lrun0 = 0.f,    lrun1 = 0.f;

    for (int kt = 0; kt < SEQ; kt += 64) {
        // Load K,V tiles (64x64 each)
#pragma unroll
        for (int l = 0; l < 8; l++) {
            int i = tid + l * 128;
            int r = i >> 4, c = (i & 15) << 2;
            float4 t = *(const float4*)(kb + (size_t)(kt + r) * HDIM + c);
            Ks[r * QPAD + c]     = f2tf32(t.x);
            Ks[r * QPAD + c + 1] = f2tf32(t.y);
            Ks[r * QPAD + c + 2] = f2tf32(t.z);
            Ks[r * QPAD + c + 3] = f2tf32(t.w);
            float4 u = *(const float4*)(vb + (size_t)(kt + r) * HDIM + c);
            Vs[r * VPAD + c]     = f2tf32(u.x);
            Vs[r * VPAD + c + 1] = f2tf32(u.y);
            Vs[r * VPAD + c + 2] = f2tf32(u.z);
            Vs[r * VPAD + c + 3] = f2tf32(u.w);
        }
        __syncthreads();

        // S = Q @ K^T  (warp: m16 x n64, k=64)
        float sacc[8][4];
#pragma unroll
        for (int j = 0; j < 8; j++)
#pragma unroll
            for (int r = 0; r < 4; r++) sacc[j][r] = 0.f;

#pragma unroll
        for (int ks = 0; ks < 8; ks++) {
            const int kk = ks * 8;
            unsigned a0 = Qs[(rowbase + gid) * QPAD + kk + tg];
            unsigned a1 = Qs[(rowbase + gid + 8) * QPAD + kk + tg];
            unsigned a2 = Qs[(rowbase + gid) * QPAD + kk + tg + 4];
            unsigned a3 = Qs[(rowbase + gid + 8) * QPAD + kk + tg + 4];
#pragma unroll
            for (int j = 0; j < 8; j++) {
                unsigned b0 = Ks[(j * 8 + gid) * QPAD + kk + tg];
                unsigned b1 = Ks[(j * 8 + gid) * QPAD + kk + tg + 4];
                mma_tf32(sacc[j], a0, a1, a2, a3, b0, b1);
            }
        }

        // Online softmax. Rows: r0 = gid, r1 = gid+8 (within warp's m16)
        float mx0 = -1e30f, mx1 = -1e30f;
#pragma unroll
        for (int j = 0; j < 8; j++) {
            mx0 = fmaxf(mx0, fmaxf(sacc[j][0], sacc[j][1]));
            mx1 = fmaxf(mx1, fmaxf(sacc[j][2], sacc[j][3]));
        }
#pragma unroll
        for (int off = 1; off <= 2; off <<= 1) {
            mx0 = fmaxf(mx0, __shfl_xor_sync(0xffffffffu, mx0, off));
            mx1 = fmaxf(mx1, __shfl_xor_sync(0xffffffffu, mx1, off));
        }
        float mn0 = fmaxf(mrun0, mx0);
        float mn1 = fmaxf(mrun1, mx1);
        float scl0 = __expf(mrun0 - mn0);
        float scl1 = __expf(mrun1 - mn1);
        mrun0 = mn0; mrun1 = mn1;

        float sum0 = 0.f, sum1 = 0.f;
#pragma unroll
        for (int j = 0; j < 8; j++) {
            float p00 = __expf(sacc[j][0] - mn0);
            float p01 = __expf(sacc[j][1] - mn0);
            float p10 = __expf(sacc[j][2] - mn1);
            float p11 = __expf(sacc[j][3] - mn1);
            sum0 += p00 + p01;
            sum1 += p10 + p11;
            int col = j * 8 + 2 * tg;
            Ps[(rowbase + gid) * QPAD + col]     = f2tf32(p00);
            Ps[(rowbase + gid) * QPAD + col + 1] = f2tf32(p01);
            Ps[(rowbase + gid + 8) * QPAD + col]     = f2tf32(p10);
            Ps[(rowbase + gid + 8) * QPAD + col + 1] = f2tf32(p11);
        }
#pragma unroll
        for (int off = 1; off <= 2; off <<= 1) {
            sum0 += __shfl_xor_sync(0xffffffffu, sum0, off);
            sum1 += __shfl_xor_sync(0xffffffffu, sum1, off);
        }
        lrun0 = lrun0 * scl0 + sum0;
        lrun1 = lrun1 * scl1 + sum1;

        // Rescale O accumulators
#pragma unroll
        for (int j = 0; j < 8; j++) {
            oacc[j][0] *= scl0; oacc[j][1] *= scl0;
            oacc[j][2] *= scl1; oacc[j][3] *= scl1;
        }
        __syncwarp();

        // O += P @ V  (warp: m16 x n64(d), k=64(keys))
#pragma unroll
        for (int ks = 0; ks < 8; ks++) {
            const int kk = ks * 8;
            unsigned a0 = Ps[(rowbase + gid) * QPAD + kk + tg];
            unsigned a1 = Ps[(rowbase + gid + 8) * QPAD + kk + tg];
            unsigned a2 = Ps[(rowbase + gid) * QPAD + kk + tg + 4];
            unsigned a3 = Ps[(rowbase + gid + 8) * QPAD + kk + tg + 4];
#pragma unroll
            for (int j = 0; j < 8; j++) {
                unsigned b0 = Vs[(kk + tg) * VPAD + j * 8 + gid];
                unsigned b1 = Vs[(kk + tg + 4) * VPAD + j * 8 + gid];
                mma_tf32(oacc[j], a0, a1, a2, a3, b0, b1);
            }
        }
        __syncthreads();
    }

    // Epilogue: normalize + write [B,N,C], C index = h*64 + d
    const int b = bh >> 4, h = bh & 15;
    float inv0 = 1.f / lrun0;
    float inv1 = 1.f / lrun1;
    int n0 = qt * 64 + rowbase + gid;
    int n1 = n0 + 8;
#pragma unroll
    for (int j = 0; j < 8; j++) {
        int d = j * 8 + 2 * tg;
        float2 v0 = make_float2(oacc[j][0] * inv0, oacc[j][1] * inv0);
        float2 v1 = make_float2(oacc[j][2] * inv1, oacc[j][3] * inv1);
        *(float2*)(g_ao + ((size_t)b * SEQ + n0) * HIDDEN + h * 64 + d) = v0;
        *(float2*)(g_ao + ((size_t)b * SEQ + n1) * HIDDEN + h * 64 + d) = v1;
    }
}

// ---------------------------------------------------------------------------
// GEMM 2: out = g_ao @ out_w^T + out_b -> d_out [8192,1024]
// ---------------------------------------------------------------------------
__global__ __launch_bounds__(256) void out_gemm_tf32(const float* __restrict__ W,
                                                     const float* __restrict__ Bi,
                                                     float* __restrict__ Out)
{
    __shared__ unsigned As[16][GPAD];
    __shared__ unsigned Bs[16][GPAD];

    const int m0 = blockIdx.y * 128;
    const int o0 = blockIdx.x * 128;
    const int tid  = threadIdx.x;
    const int wid  = tid >> 5;
    const int lane = tid & 31;
    const int gid  = lane >> 2;
    const int tg   = lane & 3;
    const int warp_m = wid >> 1;
    const int warp_n = wid & 1;

    float acc[2][8][4];
#pragma unroll
    for (int i = 0; i < 2; i++)
#pragma unroll
        for (int j = 0; j < 8; j++)
#pragma unroll
            for (int r = 0; r < 4; r++) acc[i][j][r] = 0.f;

    for (int k0 = 0; k0 < HIDDEN; k0 += 16) {
#pragma unroll
        for (int l = 0; l < 2; l++) {
            int i = tid + l * 256;
            int r = i >> 2;
            int c = (i & 3) * 4;
            float4 t = *(const float4*)(g_ao + (size_t)(m0 + r) * HIDDEN + k0 + c);
            As[c][r] = f2tf32(t.x); As[c+1][r] = f2tf32(t.y);
            As[c+2][r] = f2tf32(t.z); As[c+3][r] = f2tf32(t.w);
            float4 u = *(const float4*)(W + (size_t)(o0 + r) * HIDDEN + k0 + c);
            Bs[c][r] = f2tf32(u.x); Bs[c+1][r] = f2tf32(u.y);
            Bs[c+2][r] = f2tf32(u.z); Bs[c+3][r] = f2tf32(u.w);
        }
        __syncthreads();

#pragma unroll
        for (int ks = 0; ks < 2; ks++) {
            const int kk = ks * 8;
            unsigned a[2][4];
#pragma unroll
            for (int i = 0; i < 2; i++) {
                int rb = warp_m * 32 + i * 16 + gid;
                a[i][0] = As[kk + tg][rb];
                a[i][1] = As[kk + tg][rb + 8];
                a[i][2] = As[kk + tg + 4][rb];
                a[i][3] = As[kk + tg + 4][rb + 8];
            }
#pragma unroll
            for (int j = 0; j < 8; j++) {
                int cb = warp_n * 64 + j * 8 + gid;
                unsigned b0 = Bs[kk + tg][cb];
                unsigned b1 = Bs[kk + tg + 4][cb];
                mma_tf32(acc[0][j], a[0][0], a[0][1], a[0][2], a[0][3], b0, b1);
                mma_tf32(acc[1][j], a[1][0], a[1][1], a[1][2], a[1][3], b0, b1);
            }
        }
        __syncthreads();
    }

#pragma unroll
    for (int j = 0; j < 8; j++) {
#pragma unroll
        for (int cc = 0; cc < 2; cc++) {
            int o = o0 + warp_n * 64 + j * 8 + 2 * tg + cc;
            float bias = Bi[o];
#pragma unroll
            for (int i = 0; i < 2; i++) {
#pragma unroll
                for (int rr = 0; rr < 2; rr++) {
                    int m = m0 + warp_m * 32 + i * 16 + gid + rr * 8;
                    Out[(size_t)m * HIDDEN + o] = acc[i][j][rr * 2 + cc] + bias;
                }
            }
        }
    }
}

// ---------------------------------------------------------------------------
extern "C" void kernel_launch(void* const* d_in, const int* in_sizes, int n_in,
                              void* d_out, int out_size)
{
    const float* x     = (const float*)d_in[0];
    const float* qkv_w = (const float*)d_in[1];
    const float* qkv_b = (const float*)d_in[2];
    const float* out_w = (const float*)d_in[3];
    const float* out_b = (const float*)d_in[4];
    float* out = (float*)d_out;

    static bool attr_set = false;
    if (!attr_set) {
        cudaFuncSetAttribute(flash_attn_tf32,
                             cudaFuncAttributeMaxDynamicSharedMemorySize,
                             SM_WORDS * 4);
        attr_set = true;
    }

    qkv_gemm_tf32<<<dim3(QKV_O / 128, M_TOT / 128), 256>>>(x, qkv_w, qkv_b);
    flash_attn_tf32<<<dim3(SEQ / 64, BATCH * HEADS), 128, SM_WORDS * 4>>>();
    out_gemm_tf32<<<dim3(HIDDEN / 128, M_TOT / 128), 256>>>(out_w, out_b, out);
}

// round 5
// speedup vs baseline: 4.2485x; 1.1778x over previous
#include <cuda_runtime.h>
#include <math.h>

#define HIDDEN 1024
#define SEQ    4096
#define BATCH  2
#define HEADS  16
#define HDIM   64
#define M_TOT  (BATCH*SEQ)           // 8192
#define QKV_O  (3*HIDDEN)            // 3072

// Scratch (device globals -> BSS, no allocation)
__device__ float g_q [(size_t)BATCH*HEADS*SEQ*HDIM];
__device__ float g_k [(size_t)BATCH*HEADS*SEQ*HDIM];
__device__ float g_v [(size_t)BATCH*HEADS*SEQ*HDIM];
__device__ float g_ao[(size_t)M_TOT*HIDDEN];

// ---------------------------------------------------------------------------
// tf32 helpers
// ---------------------------------------------------------------------------
__device__ __forceinline__ unsigned f2tf32(float f) {
    unsigned r;
    asm("cvt.rna.tf32.f32 %0, %1;" : "=r"(r) : "f"(f));
    return r;
}

__device__ __forceinline__ void mma_tf32(float* c, unsigned a0, unsigned a1,
                                         unsigned a2, unsigned a3,
                                         unsigned b0, unsigned b1) {
    asm volatile(
        "mma.sync.aligned.m16n8k8.row.col.f32.tf32.tf32.f32 "
        "{%0,%1,%2,%3}, {%4,%5,%6,%7}, {%8,%9}, {%0,%1,%2,%3};"
        : "+f"(c[0]), "+f"(c[1]), "+f"(c[2]), "+f"(c[3])
        : "r"(a0), "r"(a1), "r"(a2), "r"(a3), "r"(b0), "r"(b1));
}

// ---------------------------------------------------------------------------
// GEMM core: 128x128 block, k-step 16, 128 threads = 4 warps, warp tile 64x64.
// smem [k][m], pad 140 (mod32=12): fragment loads conflict-free (12*tg+gid is
// a lane permutation), stores 2-way max. Register-prefetch pipeline on LDG.
// ---------------------------------------------------------------------------
#define GPAD 140

// ---------------------------------------------------------------------------
// GEMM 1: qkv = x @ qkv_w^T + qkv_b, scattered into g_q/g_k/g_v as [B,H,N,D]
// ---------------------------------------------------------------------------
__global__ __launch_bounds__(128) void qkv_gemm_tf32(const float* __restrict__ X,
                                                     const float* __restrict__ W,
                                                     const float* __restrict__ Bi)
{
    __shared__ unsigned As[16][GPAD];
    __shared__ unsigned Bs[16][GPAD];

    const int m0 = blockIdx.y * 128;
    const int o0 = blockIdx.x * 128;
    const int tid  = threadIdx.x;
    const int wid  = tid >> 5;
    const int lane = tid & 31;
    const int gid  = lane >> 2;
    const int tg   = lane & 3;
    const int warp_m = wid >> 1;    // 0..1, 64-row slab
    const int warp_n = wid & 1;     // 0..1, 64-col slab

    float acc[4][8][4];
#pragma unroll
    for (int mt = 0; mt < 4; mt++)
#pragma unroll
        for (int j = 0; j < 8; j++)
#pragma unroll
            for (int r = 0; r < 4; r++) acc[mt][j][r] = 0.f;

    // Prefetch k0=0 tile into registers
    float4 ar[4], br[4];
#pragma unroll
    for (int l = 0; l < 4; l++) {
        int idx = tid + l * 128;
        int r = idx >> 2;
        int c = (idx & 3) * 4;
        ar[l] = *(const float4*)(X + (size_t)(m0 + r) * HIDDEN + c);
        br[l] = *(const float4*)(W + (size_t)(o0 + r) * HIDDEN + c);
    }

    for (int k0 = 0; k0 < HIDDEN; k0 += 16) {
        __syncthreads();   // previous compute done reading smem
        // Store prefetched regs -> smem (with tf32 convert)
#pragma unroll
        for (int l = 0; l < 4; l++) {
            int idx = tid + l * 128;
            int r = idx >> 2;
            int c = (idx & 3) * 4;
            As[c][r]   = f2tf32(ar[l].x); As[c+1][r] = f2tf32(ar[l].y);
            As[c+2][r] = f2tf32(ar[l].z); As[c+3][r] = f2tf32(ar[l].w);
            Bs[c][r]   = f2tf32(br[l].x); Bs[c+1][r] = f2tf32(br[l].y);
            Bs[c+2][r] = f2tf32(br[l].z); Bs[c+3][r] = f2tf32(br[l].w);
        }
        __syncthreads();

        // Prefetch next tile (overlaps with MMA below)
        if (k0 + 16 < HIDDEN) {
#pragma unroll
            for (int l = 0; l < 4; l++) {
                int idx = tid + l * 128;
                int r = idx >> 2;
                int c = (idx & 3) * 4;
                ar[l] = *(const float4*)(X + (size_t)(m0 + r) * HIDDEN + k0 + 16 + c);
                br[l] = *(const float4*)(W + (size_t)(o0 + r) * HIDDEN + k0 + 16 + c);
            }
        }

#pragma unroll
        for (int ks = 0; ks < 2; ks++) {
            const int kk = ks * 8;
            unsigned b[8][2];
#pragma unroll
            for (int j = 0; j < 8; j++) {
                int cb = warp_n * 64 + j * 8 + gid;
                b[j][0] = Bs[kk + tg][cb];
                b[j][1] = Bs[kk + tg + 4][cb];
            }
#pragma unroll
            for (int mt = 0; mt < 4; mt++) {
                int rb = warp_m * 64 + mt * 16 + gid;
                unsigned a0 = As[kk + tg][rb];
                unsigned a1 = As[kk + tg][rb + 8];
                unsigned a2 = As[kk + tg + 4][rb];
                unsigned a3 = As[kk + tg + 4][rb + 8];
#pragma unroll
                for (int j = 0; j < 8; j++)
                    mma_tf32(acc[mt][j], a0, a1, a2, a3, b[j][0], b[j][1]);
            }
        }
    }

    // Epilogue: bias + scatter into q/k/v [B,H,N,D]
#pragma unroll
    for (int j = 0; j < 8; j++) {
#pragma unroll
        for (int cc = 0; cc < 2; cc++) {
            int o = o0 + warp_n * 64 + j * 8 + 2 * tg + cc;
            float bias = Bi[o];
            int which = o >> 10;
            int c = o & 1023;
            int h = c >> 6;
            int d = c & 63;
            float* dst = (which == 0) ? g_q : ((which == 1) ? g_k : g_v);
#pragma unroll
            for (int mt = 0; mt < 4; mt++) {
#pragma unroll
                for (int rr = 0; rr < 2; rr++) {
                    int m = m0 + warp_m * 64 + mt * 16 + gid + rr * 8;
                    int bb = m >> 12;
                    int n  = m & 4095;
                    dst[(((size_t)(bb * HEADS + h)) * SEQ + n) * HDIM + d] =
                        acc[mt][j][rr * 2 + cc] + bias;
                }
            }
        }
    }
}

// ---------------------------------------------------------------------------
// Flash attention, tf32 MMA. Q tile 128, KV tile 64. 128 threads = 4 warps,
// warp tile m32 (2x m16). Online softmax in registers, P via smem.
// ---------------------------------------------------------------------------
#define QPAD 68
#define VPAD 72
#define SM_Q  0
#define SM_K  (128*QPAD)
#define SM_V  (SM_K + 64*QPAD)
#define SM_P  (SM_V + 64*VPAD)
#define SM_WORDS (SM_P + 128*QPAD)   // 26368 words = 105472 bytes

__global__ __launch_bounds__(128) void flash_attn_tf32()
{
    extern __shared__ unsigned sm[];
    unsigned* Qs = sm + SM_Q;
    unsigned* Ks = sm + SM_K;
    unsigned* Vs = sm + SM_V;
    unsigned* Ps = sm + SM_P;

    const int bh = blockIdx.y;                 // 0..31
    const int qt = blockIdx.x;                 // 0..31 (q tile of 128)
    const int tid  = threadIdx.x;
    const int wid  = tid >> 5;                 // 0..3
    const int lane = tid & 31;
    const int gid  = lane >> 2;
    const int tg   = lane & 3;
    const int rowbase = wid * 32;
    const float scale = 0.125f;

    const float* qb = g_q + ((size_t)bh * SEQ + qt * 128) * HDIM;
    const float* kb = g_k + (size_t)bh * SEQ * HDIM;
    const float* vb = g_v + (size_t)bh * SEQ * HDIM;

    // Load + prescale Q tile (128x64)
#pragma unroll
    for (int l = 0; l < 16; l++) {
        int i = tid + l * 128;
        int r = i >> 4, c = (i & 15) << 2;
        float4 t = *(const float4*)(qb + r * HDIM + c);
        Qs[r * QPAD + c]     = f2tf32(t.x * scale);
        Qs[r * QPAD + c + 1] = f2tf32(t.y * scale);
        Qs[r * QPAD + c + 2] = f2tf32(t.z * scale);
        Qs[r * QPAD + c + 3] = f2tf32(t.w * scale);
    }

    float oacc[2][8][4];
#pragma unroll
    for (int mt = 0; mt < 2; mt++)
#pragma unroll
        for (int j = 0; j < 8; j++)
#pragma unroll
            for (int r = 0; r < 4; r++) oacc[mt][j][r] = 0.f;
    float mrun[2][2], lrun[2][2];
#pragma unroll
    for (int mt = 0; mt < 2; mt++) {
        mrun[mt][0] = -1e30f; mrun[mt][1] = -1e30f;
        lrun[mt][0] = 0.f;    lrun[mt][1] = 0.f;
    }

    for (int kt = 0; kt < SEQ; kt += 64) {
        // Load K,V tiles (64x64 each)
#pragma unroll
        for (int l = 0; l < 8; l++) {
            int i = tid + l * 128;
            int r = i >> 4, c = (i & 15) << 2;
            float4 t = *(const float4*)(kb + (size_t)(kt + r) * HDIM + c);
            Ks[r * QPAD + c]     = f2tf32(t.x);
            Ks[r * QPAD + c + 1] = f2tf32(t.y);
            Ks[r * QPAD + c + 2] = f2tf32(t.z);
            Ks[r * QPAD + c + 3] = f2tf32(t.w);
            float4 u = *(const float4*)(vb + (size_t)(kt + r) * HDIM + c);
            Vs[r * VPAD + c]     = f2tf32(u.x);
            Vs[r * VPAD + c + 1] = f2tf32(u.y);
            Vs[r * VPAD + c + 2] = f2tf32(u.z);
            Vs[r * VPAD + c + 3] = f2tf32(u.w);
        }
        __syncthreads();

        // S = Q @ K^T  (warp: m32 x n64, k=64)
        float sacc[2][8][4];
#pragma unroll
        for (int mt = 0; mt < 2; mt++)
#pragma unroll
            for (int j = 0; j < 8; j++)
#pragma unroll
                for (int r = 0; r < 4; r++) sacc[mt][j][r] = 0.f;

#pragma unroll
        for (int ks = 0; ks < 8; ks++) {
            const int kk = ks * 8;
            unsigned a[2][4];
#pragma unroll
            for (int mt = 0; mt < 2; mt++) {
                int rb = rowbase + mt * 16 + gid;
                a[mt][0] = Qs[rb * QPAD + kk + tg];
                a[mt][1] = Qs[(rb + 8) * QPAD + kk + tg];
                a[mt][2] = Qs[rb * QPAD + kk + tg + 4];
                a[mt][3] = Qs[(rb + 8) * QPAD + kk + tg + 4];
            }
#pragma unroll
            for (int j = 0; j < 8; j++) {
                unsigned b0 = Ks[(j * 8 + gid) * QPAD + kk + tg];
                unsigned b1 = Ks[(j * 8 + gid) * QPAD + kk + tg + 4];
                mma_tf32(sacc[0][j], a[0][0], a[0][1], a[0][2], a[0][3], b0, b1);
                mma_tf32(sacc[1][j], a[1][0], a[1][1], a[1][2], a[1][3], b0, b1);
            }
        }

        // Online softmax per m16 tile (rows gid, gid+8 within tile)
#pragma unroll
        for (int mt = 0; mt < 2; mt++) {
            float mx0 = -1e30f, mx1 = -1e30f;
#pragma unroll
            for (int j = 0; j < 8; j++) {
                mx0 = fmaxf(mx0, fmaxf(sacc[mt][j][0], sacc[mt][j][1]));
                mx1 = fmaxf(mx1, fmaxf(sacc[mt][j][2], sacc[mt][j][3]));
            }
#pragma unroll
            for (int off = 1; off <= 2; off <<= 1) {
                mx0 = fmaxf(mx0, __shfl_xor_sync(0xffffffffu, mx0, off));
                mx1 = fmaxf(mx1, __shfl_xor_sync(0xffffffffu, mx1, off));
            }
            float mn0 = fmaxf(mrun[mt][0], mx0);
            float mn1 = fmaxf(mrun[mt][1], mx1);
            float scl0 = __expf(mrun[mt][0] - mn0);
            float scl1 = __expf(mrun[mt][1] - mn1);
            mrun[mt][0] = mn0; mrun[mt][1] = mn1;

            int r0 = (rowbase + mt * 16 + gid) * QPAD;
            int r1 = (rowbase + mt * 16 + gid + 8) * QPAD;
            float sum0 = 0.f, sum1 = 0.f;
#pragma unroll
            for (int j = 0; j < 8; j++) {
                float p00 = __expf(sacc[mt][j][0] - mn0);
                float p01 = __expf(sacc[mt][j][1] - mn0);
                float p10 = __expf(sacc[mt][j][2] - mn1);
                float p11 = __expf(sacc[mt][j][3] - mn1);
                sum0 += p00 + p01;
                sum1 += p10 + p11;
                int col = j * 8 + 2 * tg;
                Ps[r0 + col]     = f2tf32(p00);
                Ps[r0 + col + 1] = f2tf32(p01);
                Ps[r1 + col]     = f2tf32(p10);
                Ps[r1 + col + 1] = f2tf32(p11);
            }
#pragma unroll
            for (int off = 1; off <= 2; off <<= 1) {
                sum0 += __shfl_xor_sync(0xffffffffu, sum0, off);
                sum1 += __shfl_xor_sync(0xffffffffu, sum1, off);
            }
            lrun[mt][0] = lrun[mt][0] * scl0 + sum0;
            lrun[mt][1] = lrun[mt][1] * scl1 + sum1;

            // Rescale O accumulators
#pragma unroll
            for (int j = 0; j < 8; j++) {
                oacc[mt][j][0] *= scl0; oacc[mt][j][1] *= scl0;
                oacc[mt][j][2] *= scl1; oacc[mt][j][3] *= scl1;
            }
        }
        __syncwarp();

        // O += P @ V  (warp: m32 x n64(d), k=64(keys))
#pragma unroll
        for (int ks = 0; ks < 8; ks++) {
            const int kk = ks * 8;
            unsigned a[2][4];
#pragma unroll
            for (int mt = 0; mt < 2; mt++) {
                int rb = rowbase + mt * 16 + gid;
                a[mt][0] = Ps[rb * QPAD + kk + tg];
                a[mt][1] = Ps[(rb + 8) * QPAD + kk + tg];
                a[mt][2] = Ps[rb * QPAD + kk + tg + 4];
                a[mt][3] = Ps[(rb + 8) * QPAD + kk + tg + 4];
            }
#pragma unroll
            for (int j = 0; j < 8; j++) {
                unsigned b0 = Vs[(kk + tg) * VPAD + j * 8 + gid];
                unsigned b1 = Vs[(kk + tg + 4) * VPAD + j * 8 + gid];
                mma_tf32(oacc[0][j], a[0][0], a[0][1], a[0][2], a[0][3], b0, b1);
                mma_tf32(oacc[1][j], a[1][0], a[1][1], a[1][2], a[1][3], b0, b1);
            }
        }
        __syncthreads();
    }

    // Epilogue: normalize + write [B,N,C], C index = h*64 + d
    const int b = bh >> 4, h = bh & 15;
#pragma unroll
    for (int mt = 0; mt < 2; mt++) {
        float inv0 = 1.f / lrun[mt][0];
        float inv1 = 1.f / lrun[mt][1];
        int n0 = qt * 128 + rowbase + mt * 16 + gid;
        int n1 = n0 + 8;
#pragma unroll
        for (int j = 0; j < 8; j++) {
            int d = j * 8 + 2 * tg;
            float2 v0 = make_float2(oacc[mt][j][0] * inv0, oacc[mt][j][1] * inv0);
            float2 v1 = make_float2(oacc[mt][j][2] * inv1, oacc[mt][j][3] * inv1);
            *(float2*)(g_ao + ((size_t)b * SEQ + n0) * HIDDEN + h * 64 + d) = v0;
            *(float2*)(g_ao + ((size_t)b * SEQ + n1) * HIDDEN + h * 64 + d) = v1;
        }
    }
}

// ---------------------------------------------------------------------------
// GEMM 2: out = g_ao @ out_w^T + out_b -> d_out [8192,1024]
// ---------------------------------------------------------------------------
__global__ __launch_bounds__(128) void out_gemm_tf32(const float* __restrict__ W,
                                                     const float* __restrict__ Bi,
                                                     float* __restrict__ Out)
{
    __shared__ unsigned As[16][GPAD];
    __shared__ unsigned Bs[16][GPAD];

    const int m0 = blockIdx.y * 128;
    const int o0 = blockIdx.x * 128;
    const int tid  = threadIdx.x;
    const int wid  = tid >> 5;
    const int lane = tid & 31;
    const int gid  = lane >> 2;
    const int tg   = lane & 3;
    const int warp_m = wid >> 1;
    const int warp_n = wid & 1;

    float acc[4][8][4];
#pragma unroll
    for (int mt = 0; mt < 4; mt++)
#pragma unroll
        for (int j = 0; j < 8; j++)
#pragma unroll
            for (int r = 0; r < 4; r++) acc[mt][j][r] = 0.f;

    float4 ar[4], br[4];
#pragma unroll
    for (int l = 0; l < 4; l++) {
        int idx = tid + l * 128;
        int r = idx >> 2;
        int c = (idx & 3) * 4;
        ar[l] = *(const float4*)(g_ao + (size_t)(m0 + r) * HIDDEN + c);
        br[l] = *(const float4*)(W + (size_t)(o0 + r) * HIDDEN + c);
    }

    for (int k0 = 0; k0 < HIDDEN; k0 += 16) {
        __syncthreads();
#pragma unroll
        for (int l = 0; l < 4; l++) {
            int idx = tid + l * 128;
            int r = idx >> 2;
            int c = (idx & 3) * 4;
            As[c][r]   = f2tf32(ar[l].x); As[c+1][r] = f2tf32(ar[l].y);
            As[c+2][r] = f2tf32(ar[l].z); As[c+3][r] = f2tf32(ar[l].w);
            Bs[c][r]   = f2tf32(br[l].x); Bs[c+1][r] = f2tf32(br[l].y);
            Bs[c+2][r] = f2tf32(br[l].z); Bs[c+3][r] = f2tf32(br[l].w);
        }
        __syncthreads();

        if (k0 + 16 < HIDDEN) {
#pragma unroll
            for (int l = 0; l < 4; l++) {
                int idx = tid + l * 128;
                int r = idx >> 2;
                int c = (idx & 3) * 4;
                ar[l] = *(const float4*)(g_ao + (size_t)(m0 + r) * HIDDEN + k0 + 16 + c);
                br[l] = *(const float4*)(W + (size_t)(o0 + r) * HIDDEN + k0 + 16 + c);
            }
        }

#pragma unroll
        for (int ks = 0; ks < 2; ks++) {
            const int kk = ks * 8;
            unsigned b[8][2];
#pragma unroll
            for (int j = 0; j < 8; j++) {
                int cb = warp_n * 64 + j * 8 + gid;
                b[j][0] = Bs[kk + tg][cb];
                b[j][1] = Bs[kk + tg + 4][cb];
            }
#pragma unroll
            for (int mt = 0; mt < 4; mt++) {
                int rb = warp_m * 64 + mt * 16 + gid;
                unsigned a0 = As[kk + tg][rb];
                unsigned a1 = As[kk + tg][rb + 8];
                unsigned a2 = As[kk + tg + 4][rb];
                unsigned a3 = As[kk + tg + 4][rb + 8];
#pragma unroll
                for (int j = 0; j < 8; j++)
                    mma_tf32(acc[mt][j], a0, a1, a2, a3, b[j][0], b[j][1]);
            }
        }
    }

#pragma unroll
    for (int j = 0; j < 8; j++) {
#pragma unroll
        for (int cc = 0; cc < 2; cc++) {
            int o = o0 + warp_n * 64 + j * 8 + 2 * tg + cc;
            float bias = Bi[o];
#pragma unroll
            for (int mt = 0; mt < 4; mt++) {
#pragma unroll
                for (int rr = 0; rr < 2; rr++) {
                    int m = m0 + warp_m * 64 + mt * 16 + gid + rr * 8;
                    Out[(size_t)m * HIDDEN + o] = acc[mt][j][rr * 2 + cc] + bias;
                }
            }
        }
    }
}

// ---------------------------------------------------------------------------
extern "C" void kernel_launch(void* const* d_in, const int* in_sizes, int n_in,
                              void* d_out, int out_size)
{
    const float* x     = (const float*)d_in[0];
    const float* qkv_w = (const float*)d_in[1];
    const float* qkv_b = (const float*)d_in[2];
    const float* out_w = (const float*)d_in[3];
    const float* out_b = (const float*)d_in[4];
    float* out = (float*)d_out;

    static bool attr_set = false;
    if (!attr_set) {
        cudaFuncSetAttribute(flash_attn_tf32,
                             cudaFuncAttributeMaxDynamicSharedMemorySize,
                             SM_WORDS * 4);
        attr_set = true;
    }

    qkv_gemm_tf32<<<dim3(QKV_O / 128, M_TOT / 128), 128>>>(x, qkv_w, qkv_b);
    flash_attn_tf32<<<dim3(SEQ / 128, BATCH * HEADS), 128, SM_WORDS * 4>>>();
    out_gemm_tf32<<<dim3(HIDDEN / 128, M_TOT / 128), 128>>>(out_w, out_b, out);
}

// round 7
// speedup vs baseline: 9.0557x; 2.1315x over previous
#include <cuda_runtime.h>
#include <cuda_fp16.h>
#include <math.h>

#define HIDDEN 1024
#define SEQ    4096
#define BATCH  2
#define HEADS  16
#define HDIM   64
#define M_TOT  (BATCH*SEQ)           // 8192
#define QKV_O  (3*HIDDEN)            // 3072

// Scratch (device globals -> BSS, no allocation). All fp16.
__device__ __half g_q [(size_t)BATCH*HEADS*SEQ*HDIM];
__device__ __half g_k [(size_t)BATCH*HEADS*SEQ*HDIM];
__device__ __half g_v [(size_t)BATCH*HEADS*SEQ*HDIM];
__device__ __half g_ao[(size_t)M_TOT*HIDDEN];

// ---------------------------------------------------------------------------
// helpers
// ---------------------------------------------------------------------------
__device__ __forceinline__ unsigned smem_u32(const void* p) {
    return (unsigned)__cvta_generic_to_shared(p);
}

__device__ __forceinline__ void ldsm4(unsigned& r0, unsigned& r1,
                                      unsigned& r2, unsigned& r3, unsigned addr) {
    asm volatile("ldmatrix.sync.aligned.m8n8.x4.shared.b16 {%0,%1,%2,%3}, [%4];"
                 : "=r"(r0), "=r"(r1), "=r"(r2), "=r"(r3) : "r"(addr));
}
__device__ __forceinline__ void ldsm4t(unsigned& r0, unsigned& r1,
                                       unsigned& r2, unsigned& r3, unsigned addr) {
    asm volatile("ldmatrix.sync.aligned.m8n8.x4.trans.shared.b16 {%0,%1,%2,%3}, [%4];"
                 : "=r"(r0), "=r"(r1), "=r"(r2), "=r"(r3) : "r"(addr));
}

__device__ __forceinline__ void mma_fp16(float* c, unsigned a0, unsigned a1,
                                         unsigned a2, unsigned a3,
                                         unsigned b0, unsigned b1) {
    asm volatile(
        "mma.sync.aligned.m16n8k16.row.col.f32.f16.f16.f32 "
        "{%0,%1,%2,%3}, {%4,%5,%6,%7}, {%8,%9}, {%0,%1,%2,%3};"
        : "+f"(c[0]), "+f"(c[1]), "+f"(c[2]), "+f"(c[3])
        : "r"(a0), "r"(a1), "r"(a2), "r"(a3), "r"(b0), "r"(b1));
}

__device__ __forceinline__ unsigned pack_h2(float lo, float hi) {
    __half2 h = __floats2half2_rn(lo, hi);
    return *reinterpret_cast<unsigned*>(&h);
}

// ---------------------------------------------------------------------------
// GEMM core: 128x128 block, k-step 16, 128 threads = 4 warps, warp tile 64x64.
// smem [row][k] halfs, row stride 24 (16 + 8 pad) -> ldmatrix conflict-free.
// ---------------------------------------------------------------------------
#define ASTR 24

// ---------------------------------------------------------------------------
// GEMM 1: qkv = x @ qkv_w^T + qkv_b -> scatter (fp16) into g_q/g_k/g_v [B,H,N,D]
// q is pre-scaled by 1/sqrt(D) here.
// ---------------------------------------------------------------------------
__global__ __launch_bounds__(128) void qkv_gemm_fp16(const float* __restrict__ X,
                                                     const float* __restrict__ W,
                                                     const float* __restrict__ Bi)
{
    __shared__ __align__(16) __half As[128 * ASTR];
    __shared__ __align__(16) __half Bs[128 * ASTR];

    const int m0 = blockIdx.y * 128;
    const int o0 = blockIdx.x * 128;
    const int tid  = threadIdx.x;
    const int wid  = tid >> 5;
    const int lane = tid & 31;
    const int gid  = lane >> 2;
    const int tg   = lane & 3;
    const int warp_m = wid >> 1;
    const int warp_n = wid & 1;

    // ldmatrix lane maps
    const int a_row  = (lane & 7) + ((lane >> 3) & 1) * 8;
    const int a_ksel = (lane >> 4) * 8;
    const int b_row  = (lane & 7) + (lane >> 4) * 8;
    const int b_ksel = ((lane >> 3) & 1) * 8;
    const unsigned aBase = smem_u32(As) + ((warp_m * 64 + a_row) * ASTR + a_ksel) * 2;
    const unsigned bBase = smem_u32(Bs) + ((warp_n * 64 + b_row) * ASTR + b_ksel) * 2;

    float acc[4][8][4];
#pragma unroll
    for (int mt = 0; mt < 4; mt++)
#pragma unroll
        for (int j = 0; j < 8; j++)
#pragma unroll
            for (int r = 0; r < 4; r++) acc[mt][j][r] = 0.f;

    float4 ar[4], br[4];
#pragma unroll
    for (int l = 0; l < 4; l++) {
        int idx = tid + l * 128;
        int r = idx >> 2, c = (idx & 3) * 4;
        ar[l] = *(const float4*)(X + (size_t)(m0 + r) * HIDDEN + c);
        br[l] = *(const float4*)(W + (size_t)(o0 + r) * HIDDEN + c);
    }

    for (int k0 = 0; k0 < HIDDEN; k0 += 16) {
        __syncthreads();
#pragma unroll
        for (int l = 0; l < 4; l++) {
            int idx = tid + l * 128;
            int r = idx >> 2, c = (idx & 3) * 4;
            *(uint2*)&As[r * ASTR + c] =
                make_uint2(pack_h2(ar[l].x, ar[l].y), pack_h2(ar[l].z, ar[l].w));
            *(uint2*)&Bs[r * ASTR + c] =
                make_uint2(pack_h2(br[l].x, br[l].y), pack_h2(br[l].z, br[l].w));
        }
        __syncthreads();

        if (k0 + 16 < HIDDEN) {
#pragma unroll
            for (int l = 0; l < 4; l++) {
                int idx = tid + l * 128;
                int r = idx >> 2, c = (idx & 3) * 4;
                ar[l] = *(const float4*)(X + (size_t)(m0 + r) * HIDDEN + k0 + 16 + c);
                br[l] = *(const float4*)(W + (size_t)(o0 + r) * HIDDEN + k0 + 16 + c);
            }
        }

        unsigned bb[4][4];
#pragma unroll
        for (int jt = 0; jt < 4; jt++)
            ldsm4(bb[jt][0], bb[jt][1], bb[jt][2], bb[jt][3], bBase + jt * 16 * ASTR * 2);
#pragma unroll
        for (int mt = 0; mt < 4; mt++) {
            unsigned a0, a1, a2, a3;
            ldsm4(a0, a1, a2, a3, aBase + mt * 16 * ASTR * 2);
#pragma unroll
            for (int jt = 0; jt < 4; jt++) {
                mma_fp16(acc[mt][2 * jt],     a0, a1, a2, a3, bb[jt][0], bb[jt][1]);
                mma_fp16(acc[mt][2 * jt + 1], a0, a1, a2, a3, bb[jt][2], bb[jt][3]);
            }
        }
    }

    // Epilogue: bias (+0.125 scale for q) -> half2 scatter into [B,H,N,D]
#pragma unroll
    for (int j = 0; j < 8; j++) {
        int o = o0 + warp_n * 64 + j * 8 + 2 * tg;   // even
        float b0f = Bi[o], b1f = Bi[o + 1];
        int which = o >> 10;
        int c = o & 1023;
        int h = c >> 6;
        int d = c & 63;                               // even
        float sc = (which == 0) ? 0.125f : 1.f;
        __half* dst = (which == 0) ? g_q : ((which == 1) ? g_k : g_v);
#pragma unroll
        for (int mt = 0; mt < 4; mt++) {
#pragma unroll
            for (int rr = 0; rr < 2; rr++) {
                int m = m0 + warp_m * 64 + mt * 16 + gid + rr * 8;
                int bb_ = m >> 12;
                int n  = m & 4095;
                float v0 = (acc[mt][j][rr * 2]     + b0f) * sc;
                float v1 = (acc[mt][j][rr * 2 + 1] + b1f) * sc;
                *(__half2*)(dst + (((size_t)(bb_ * HEADS + h)) * SEQ + n) * HDIM + d) =
                    __floats2half2_rn(v0, v1);
            }
        }
    }
}

// ---------------------------------------------------------------------------
// Flash attention fp16. Q tile 128, KV tile 64, 128 threads = 4 warps (m32).
// P kept in registers (S-accum frag == A frag for PV). smem halfs, stride 72.
// ---------------------------------------------------------------------------
#define FSTR 72

__global__ __launch_bounds__(128) void flash_attn_fp16()
{
    __shared__ __align__(16) __half Qs[128 * FSTR];
    __shared__ __align__(16) __half Ks[64 * FSTR];
    __shared__ __align__(16) __half Vs[64 * FSTR];

    const int bh = blockIdx.y;
    const int qt = blockIdx.x;
    const int tid  = threadIdx.x;
    const int wid  = tid >> 5;
    const int lane = tid & 31;
    const int gid  = lane >> 2;
    const int tg   = lane & 3;
    const int rowbase = wid * 32;

    const int a_row  = (lane & 7) + ((lane >> 3) & 1) * 8;
    const int a_ksel = (lane >> 4) * 8;
    const int b_row  = (lane & 7) + (lane >> 4) * 8;
    const int b_ksel = ((lane >> 3) & 1) * 8;

    const __half* qb = g_q + ((size_t)bh * SEQ + qt * 128) * HDIM;
    const __half* kb = g_k + (size_t)bh * SEQ * HDIM;
    const __half* vb = g_v + (size_t)bh * SEQ * HDIM;

    // Load Q tile (128x64 halfs) — already prescaled
#pragma unroll
    for (int l = 0; l < 8; l++) {
        int i = tid + l * 128;
        int r = i >> 3, c = (i & 7) * 8;
        *(uint4*)&Qs[r * FSTR + c] = *(const uint4*)(qb + r * HDIM + c);
    }

    // fragment addr bases
    const unsigned qBase = smem_u32(Qs) + ((rowbase + a_row) * FSTR + a_ksel) * 2;
    const unsigned kBase = smem_u32(Ks) + (b_row * FSTR + b_ksel) * 2;
    const unsigned vBase = smem_u32(Vs) + (a_row * FSTR + a_ksel) * 2;

    float oacc[2][8][4];
#pragma unroll
    for (int mt = 0; mt < 2; mt++)
#pragma unroll
        for (int j = 0; j < 8; j++)
#pragma unroll
            for (int r = 0; r < 4; r++) oacc[mt][j][r] = 0.f;
    float mrun[2][2], lrun[2][2];
#pragma unroll
    for (int mt = 0; mt < 2; mt++) {
        mrun[mt][0] = -1e30f; mrun[mt][1] = -1e30f;
        lrun[mt][0] = 0.f;    lrun[mt][1] = 0.f;
    }

    // prefetch first KV tile
    uint4 kr[4], vr[4];
#pragma unroll
    for (int l = 0; l < 4; l++) {
        int i = tid + l * 128;
        int r = i >> 3, c = (i & 7) * 8;
        kr[l] = *(const uint4*)(kb + (size_t)r * HDIM + c);
        vr[l] = *(const uint4*)(vb + (size_t)r * HDIM + c);
    }

    for (int kt = 0; kt < SEQ; kt += 64) {
        __syncthreads();
#pragma unroll
        for (int l = 0; l < 4; l++) {
            int i = tid + l * 128;
            int r = i >> 3, c = (i & 7) * 8;
            *(uint4*)&Ks[r * FSTR + c] = kr[l];
            *(uint4*)&Vs[r * FSTR + c] = vr[l];
        }
        __syncthreads();

        if (kt + 64 < SEQ) {
#pragma unroll
            for (int l = 0; l < 4; l++) {
                int i = tid + l * 128;
                int r = i >> 3, c = (i & 7) * 8;
                kr[l] = *(const uint4*)(kb + (size_t)(kt + 64 + r) * HDIM + c);
                vr[l] = *(const uint4*)(vb + (size_t)(kt + 64 + r) * HDIM + c);
            }
        }

        // ---- S = Q @ K^T  (warp m32 x n64, k=64) ----
        float sacc[2][8][4];
#pragma unroll
        for (int mt = 0; mt < 2; mt++)
#pragma unroll
            for (int j = 0; j < 8; j++)
#pragma unroll
                for (int r = 0; r < 4; r++) sacc[mt][j][r] = 0.f;

#pragma unroll
        for (int ks = 0; ks < 4; ks++) {
            unsigned bb[4][4];
#pragma unroll
            for (int jt = 0; jt < 4; jt++)
                ldsm4(bb[jt][0], bb[jt][1], bb[jt][2], bb[jt][3],
                      kBase + (jt * 16 * FSTR + ks * 16) * 2);
#pragma unroll
            for (int mt = 0; mt < 2; mt++) {
                unsigned a0, a1, a2, a3;
                ldsm4(a0, a1, a2, a3, qBase + (mt * 16 * FSTR + ks * 16) * 2);
#pragma unroll
                for (int jt = 0; jt < 4; jt++) {
                    mma_fp16(sacc[mt][2 * jt],     a0, a1, a2, a3, bb[jt][0], bb[jt][1]);
                    mma_fp16(sacc[mt][2 * jt + 1], a0, a1, a2, a3, bb[jt][2], bb[jt][3]);
                }
            }
        }

        // ---- online softmax; P packed into registers ----
        unsigned ph0[2][8], ph1[2][8];
#pragma unroll
        for (int mt = 0; mt < 2; mt++) {
            float mx0 = -1e30f, mx1 = -1e30f;
#pragma unroll
            for (int j = 0; j < 8; j++) {
                mx0 = fmaxf(mx0, fmaxf(sacc[mt][j][0], sacc[mt][j][1]));
                mx1 = fmaxf(mx1, fmaxf(sacc[mt][j][2], sacc[mt][j][3]));
            }
#pragma unroll
            for (int off = 1; off <= 2; off <<= 1) {
                mx0 = fmaxf(mx0, __shfl_xor_sync(0xffffffffu, mx0, off));
                mx1 = fmaxf(mx1, __shfl_xor_sync(0xffffffffu, mx1, off));
            }
            float mn0 = fmaxf(mrun[mt][0], mx0);
            float mn1 = fmaxf(mrun[mt][1], mx1);
            float scl0 = __expf(mrun[mt][0] - mn0);
            float scl1 = __expf(mrun[mt][1] - mn1);
            mrun[mt][0] = mn0; mrun[mt][1] = mn1;

            float sum0 = 0.f, sum1 = 0.f;
#pragma unroll
            for (int j = 0; j < 8; j++) {
                float p00 = __expf(sacc[mt][j][0] - mn0);
                float p01 = __expf(sacc[mt][j][1] - mn0);
                float p10 = __expf(sacc[mt][j][2] - mn1);
                float p11 = __expf(sacc[mt][j][3] - mn1);
                sum0 += p00 + p01;
                sum1 += p10 + p11;
                ph0[mt][j] = pack_h2(p00, p01);
                ph1[mt][j] = pack_h2(p10, p11);
            }
#pragma unroll
            for (int off = 1; off <= 2; off <<= 1) {
                sum0 += __shfl_xor_sync(0xffffffffu, sum0, off);
                sum1 += __shfl_xor_sync(0xffffffffu, sum1, off);
            }
            lrun[mt][0] = lrun[mt][0] * scl0 + sum0;
            lrun[mt][1] = lrun[mt][1] * scl1 + sum1;

#pragma unroll
            for (int j = 0; j < 8; j++) {
                oacc[mt][j][0] *= scl0; oacc[mt][j][1] *= scl0;
                oacc[mt][j][2] *= scl1; oacc[mt][j][3] *= scl1;
            }
        }

        // ---- O += P @ V  (k = 64 keys; A-frags direct from ph regs) ----
#pragma unroll
        for (int kb2 = 0; kb2 < 4; kb2++) {
            unsigned vv[4][4];
#pragma unroll
            for (int jt = 0; jt < 4; jt++)
                ldsm4t(vv[jt][0], vv[jt][1], vv[jt][2], vv[jt][3],
                       vBase + (kb2 * 16 * FSTR + jt * 16) * 2);
#pragma unroll
            for (int mt = 0; mt < 2; mt++) {
                unsigned a0 = ph0[mt][2 * kb2];
                unsigned a1 = ph1[mt][2 * kb2];
                unsigned a2 = ph0[mt][2 * kb2 + 1];
                unsigned a3 = ph1[mt][2 * kb2 + 1];
#pragma unroll
                for (int jt = 0; jt < 4; jt++) {
                    mma_fp16(oacc[mt][2 * jt],     a0, a1, a2, a3, vv[jt][0], vv[jt][1]);
                    mma_fp16(oacc[mt][2 * jt + 1], a0, a1, a2, a3, vv[jt][2], vv[jt][3]);
                }
            }
        }
    }

    // Epilogue: normalize, write half2 into g_ao [B,N,C]
    const int b = bh >> 4, h = bh & 15;
#pragma unroll
    for (int mt = 0; mt < 2; mt++) {
        float inv0 = 1.f / lrun[mt][0];
        float inv1 = 1.f / lrun[mt][1];
        int n0 = qt * 128 + rowbase + mt * 16 + gid;
        int n1 = n0 + 8;
#pragma unroll
        for (int j = 0; j < 8; j++) {
            int d = j * 8 + 2 * tg;
            *(__half2*)(g_ao + ((size_t)b * SEQ + n0) * HIDDEN + h * 64 + d) =
                __floats2half2_rn(oacc[mt][j][0] * inv0, oacc[mt][j][1] * inv0);
            *(__half2*)(g_ao + ((size_t)b * SEQ + n1) * HIDDEN + h * 64 + d) =
                __floats2half2_rn(oacc[mt][j][2] * inv1, oacc[mt][j][3] * inv1);
        }
    }
}

// ---------------------------------------------------------------------------
// GEMM 2: out = g_ao(half) @ out_w^T + out_b -> d_out (fp32) [8192,1024]
// ---------------------------------------------------------------------------
__global__ __launch_bounds__(128) void out_gemm_fp16(const float* __restrict__ W,
                                                     const float* __restrict__ Bi,
                                                     float* __restrict__ Out)
{
    __shared__ __align__(16) __half As[128 * ASTR];
    __shared__ __align__(16) __half Bs[128 * ASTR];

    const int m0 = blockIdx.y * 128;
    const int o0 = blockIdx.x * 128;
    const int tid  = threadIdx.x;
    const int wid  = tid >> 5;
    const int lane = tid & 31;
    const int gid  = lane >> 2;
    const int tg   = lane & 3;
    const int warp_m = wid >> 1;
    const int warp_n = wid & 1;

    const int a_row  = (lane & 7) + ((lane >> 3) & 1) * 8;
    const int a_ksel = (lane >> 4) * 8;
    const int b_row  = (lane & 7) + (lane >> 4) * 8;
    const int b_ksel = ((lane >> 3) & 1) * 8;
    const unsigned aBase = smem_u32(As) + ((warp_m * 64 + a_row) * ASTR + a_ksel) * 2;
    const unsigned bBase = smem_u32(Bs) + ((warp_n * 64 + b_row) * ASTR + b_ksel) * 2;

    float acc[4][8][4];
#pragma unroll
    for (int mt = 0; mt < 4; mt++)
#pragma unroll
        for (int j = 0; j < 8; j++)
#pragma unroll
            for (int r = 0; r < 4; r++) acc[mt][j][r] = 0.f;

    // A tile: 128 rows x 16 halfs = 256 uint4 -> TWO uint4 per thread (bugfix).
    // B: fp32, 4 float4 per thread.
    uint4  ar[2];
    float4 br[4];
    {
#pragma unroll
        for (int l = 0; l < 2; l++) {
            int idx = tid + l * 128;
            int rA = idx >> 1, cA = (idx & 1) * 8;
            ar[l] = *(const uint4*)(g_ao + (size_t)(m0 + rA) * HIDDEN + cA);
        }
#pragma unroll
        for (int l = 0; l < 4; l++) {
            int idx = tid + l * 128;
            int r = idx >> 2, c = (idx & 3) * 4;
            br[l] = *(const float4*)(W + (size_t)(o0 + r) * HIDDEN + c);
        }
    }

    for (int k0 = 0; k0 < HIDDEN; k0 += 16) {
        __syncthreads();
        {
#pragma unroll
            for (int l = 0; l < 2; l++) {
                int idx = tid + l * 128;
                int rA = idx >> 1, cA = (idx & 1) * 8;
                *(uint4*)&As[rA * ASTR + cA] = ar[l];
            }
#pragma unroll
            for (int l = 0; l < 4; l++) {
                int idx = tid + l * 128;
                int r = idx >> 2, c = (idx & 3) * 4;
                *(uint2*)&Bs[r * ASTR + c] =
                    make_uint2(pack_h2(br[l].x, br[l].y), pack_h2(br[l].z, br[l].w));
            }
        }
        __syncthreads();

        if (k0 + 16 < HIDDEN) {
#pragma unroll
            for (int l = 0; l < 2; l++) {
                int idx = tid + l * 128;
                int rA = idx >> 1, cA = (idx & 1) * 8;
                ar[l] = *(const uint4*)(g_ao + (size_t)(m0 + rA) * HIDDEN + k0 + 16 + cA);
            }
#pragma unroll
            for (int l = 0; l < 4; l++) {
                int idx = tid + l * 128;
                int r = idx >> 2, c = (idx & 3) * 4;
                br[l] = *(const float4*)(W + (size_t)(o0 + r) * HIDDEN + k0 + 16 + c);
            }
        }

        unsigned bb[4][4];
#pragma unroll
        for (int jt = 0; jt < 4; jt++)
            ldsm4(bb[jt][0], bb[jt][1], bb[jt][2], bb[jt][3], bBase + jt * 16 * ASTR * 2);
#pragma unroll
        for (int mt = 0; mt < 4; mt++) {
            unsigned a0, a1, a2, a3;
            ldsm4(a0, a1, a2, a3, aBase + mt * 16 * ASTR * 2);
#pragma unroll
            for (int jt = 0; jt < 4; jt++) {
                mma_fp16(acc[mt][2 * jt],     a0, a1, a2, a3, bb[jt][0], bb[jt][1]);
                mma_fp16(acc[mt][2 * jt + 1], a0, a1, a2, a3, bb[jt][2], bb[jt][3]);
            }
        }
    }

#pragma unroll
    for (int j = 0; j < 8; j++) {
        int o = o0 + warp_n * 64 + j * 8 + 2 * tg;    // even
        float b0f = Bi[o], b1f = Bi[o + 1];
#pragma unroll
        for (int mt = 0; mt < 4; mt++) {
#pragma unroll
            for (int rr = 0; rr < 2; rr++) {
                int m = m0 + warp_m * 64 + mt * 16 + gid + rr * 8;
                *(float2*)(Out + (size_t)m * HIDDEN + o) =
                    make_float2(acc[mt][j][rr * 2] + b0f, acc[mt][j][rr * 2 + 1] + b1f);
            }
        }
    }
}

// ---------------------------------------------------------------------------
extern "C" void kernel_launch(void* const* d_in, const int* in_sizes, int n_in,
                              void* d_out, int out_size)
{
    const float* x     = (const float*)d_in[0];
    const float* qkv_w = (const float*)d_in[1];
    const float* qkv_b = (const float*)d_in[2];
    const float* out_w = (const float*)d_in[3];
    const float* out_b = (const float*)d_in[4];
    float* out = (float*)d_out;

    qkv_gemm_fp16<<<dim3(QKV_O / 128, M_TOT / 128), 128>>>(x, qkv_w, qkv_b);
    flash_attn_fp16<<<dim3(SEQ / 128, BATCH * HEADS), 128>>>();
    out_gemm_fp16<<<dim3(HIDDEN / 128, M_TOT / 128), 128>>>(out_w, out_b, out);
}

// round 10
// speedup vs baseline: 10.5461x; 1.1646x over previous
#include <cuda_runtime.h>
#include <cuda_fp16.h>
#include <math.h>

#define HIDDEN 1024
#define SEQ    4096
#define BATCH  2
#define HEADS  16
#define HDIM   64
#define M_TOT  (BATCH*SEQ)           // 8192
#define QKV_O  (3*HIDDEN)            // 3072

// Scratch (device globals -> BSS, no allocation). All fp16.
__device__ __half g_q [(size_t)BATCH*HEADS*SEQ*HDIM];
__device__ __half g_k [(size_t)BATCH*HEADS*SEQ*HDIM];
__device__ __half g_v [(size_t)BATCH*HEADS*SEQ*HDIM];
__device__ __half g_ao[(size_t)M_TOT*HIDDEN];
__device__ __half g_xh [(size_t)M_TOT*HIDDEN];
__device__ __half g_wqh[(size_t)QKV_O*HIDDEN];
__device__ __half g_woh[(size_t)HIDDEN*HIDDEN];

// ---------------------------------------------------------------------------
// helpers
// ---------------------------------------------------------------------------
__device__ __forceinline__ unsigned smem_u32(const void* p) {
    return (unsigned)__cvta_generic_to_shared(p);
}
__device__ __forceinline__ unsigned pack_h2(float lo, float hi) {
    __half2 h = __floats2half2_rn(lo, hi);
    return *reinterpret_cast<unsigned*>(&h);
}
__device__ __forceinline__ void cpa16(unsigned dst, const void* src) {
    asm volatile("cp.async.cg.shared.global [%0], [%1], 16;"
                 :: "r"(dst), "l"(__cvta_generic_to_global(src)) : "memory");
}
#define CP_COMMIT() asm volatile("cp.async.commit_group;" ::: "memory")
#define CP_WAIT1()  asm volatile("cp.async.wait_group 1;" ::: "memory")

__device__ __forceinline__ void ldsm4(unsigned& r0, unsigned& r1,
                                      unsigned& r2, unsigned& r3, unsigned addr) {
    asm volatile("ldmatrix.sync.aligned.m8n8.x4.shared.b16 {%0,%1,%2,%3}, [%4];"
                 : "=r"(r0), "=r"(r1), "=r"(r2), "=r"(r3) : "r"(addr));
}
__device__ __forceinline__ void ldsm4t(unsigned& r0, unsigned& r1,
                                       unsigned& r2, unsigned& r3, unsigned addr) {
    asm volatile("ldmatrix.sync.aligned.m8n8.x4.trans.shared.b16 {%0,%1,%2,%3}, [%4];"
                 : "=r"(r0), "=r"(r1), "=r"(r2), "=r"(r3) : "r"(addr));
}
__device__ __forceinline__ void mma_fp16(float* c, unsigned a0, unsigned a1,
                                         unsigned a2, unsigned a3,
                                         unsigned b0, unsigned b1) {
    asm volatile(
        "mma.sync.aligned.m16n8k16.row.col.f32.f16.f16.f32 "
        "{%0,%1,%2,%3}, {%4,%5,%6,%7}, {%8,%9}, {%0,%1,%2,%3};"
        : "+f"(c[0]), "+f"(c[1]), "+f"(c[2]), "+f"(c[3])
        : "r"(a0), "r"(a1), "r"(a2), "r"(a3), "r"(b0), "r"(b1));
}

// ---------------------------------------------------------------------------
// fp32 -> fp16 convert (x, qkv_w, out_w)
// ---------------------------------------------------------------------------
__global__ void cvt_fp16(const float* __restrict__ src, int which, int n)
{
    __half* dst = (which == 0) ? g_xh : (which == 1) ? g_wqh : g_woh;
    int i = blockIdx.x * blockDim.x + threadIdx.x;
    int stride = gridDim.x * blockDim.x;
    for (int idx = i; idx < n / 4; idx += stride) {
        float4 v = ((const float4*)src)[idx];
        ((uint2*)dst)[idx] = make_uint2(pack_h2(v.x, v.y), pack_h2(v.z, v.w));
    }
}

// ---------------------------------------------------------------------------
// GEMM: D[M_TOT, Ncols] = A(fp16) @ B(fp16)^T + bias
// mode 0: A=g_xh, B=g_wqh -> scatter to g_q/g_k/g_v (q pre-scaled by 0.125)
// mode 1: A=g_ao, B=g_woh -> OutF fp32
// Block 128x128, 128 thr = 4 warps (warp tile 64x64), K-chunk 32, 3-stage
// cp.async ring. smem rows 40 halfs (80B) -> ldmatrix conflict-free.
// ---------------------------------------------------------------------------
#define KC       32
#define GROWB    80                   // bytes per smem row
#define GST_A    (128*GROWB)          // 10240
#define GST_ST   (2*GST_A)            // 20480 per stage (A+B)
#define G_DSMEM  (3*GST_ST)           // 61440
#define NSTG_G   (HIDDEN/KC)          // 32

__global__ __launch_bounds__(128) void gemm_tc(const float* __restrict__ Bi,
                                               float* __restrict__ OutF,
                                               int mode)
{
    extern __shared__ __align__(16) char gsm[];
    const __half* Am = (mode == 1) ? g_ao  : g_xh;
    const __half* Bm = (mode == 1) ? g_woh : g_wqh;

    const unsigned sbase = smem_u32(gsm);
    const int tid  = threadIdx.x;
    const int wid  = tid >> 5;
    const int lane = tid & 31;
    const int gid  = lane >> 2;
    const int tg   = lane & 3;
    const int warp_m = wid >> 1;
    const int warp_n = wid & 1;
    const int m0 = blockIdx.y * 128;
    const int o0 = blockIdx.x * 128;

    // ldmatrix lane maps (identical to round-7 verified layout)
    const int a_row  = (lane & 7) + ((lane >> 3) & 1) * 8;
    const int a_ksel = (lane >> 4) * 8;
    const int b_row  = (lane & 7) + (lane >> 4) * 8;
    const int b_ksel = ((lane >> 3) & 1) * 8;
    const unsigned aFrag = sbase + (warp_m * 64 + a_row) * GROWB + a_ksel * 2;
    const unsigned bFrag = sbase + GST_A + (warp_n * 64 + b_row) * GROWB + b_ksel * 2;

    float acc[4][8][4];
#pragma unroll
    for (int mt = 0; mt < 4; mt++)
#pragma unroll
        for (int j = 0; j < 8; j++)
#pragma unroll
            for (int r = 0; r < 4; r++) acc[mt][j][r] = 0.f;

    auto issue = [&](int kt, int s) {
        unsigned ab = sbase + s * GST_ST;
        unsigned bb = ab + GST_A;
        const __half* as = Am + (size_t)m0 * HIDDEN + kt * KC;
        const __half* bs = Bm + (size_t)o0 * HIDDEN + kt * KC;
#pragma unroll
        for (int l = 0; l < 4; l++) {
            int idx = tid + l * 128;         // 0..511
            int r = idx >> 2, c = idx & 3;
            cpa16(ab + r * GROWB + c * 16, as + (size_t)r * HIDDEN + c * 8);
            cpa16(bb + r * GROWB + c * 16, bs + (size_t)r * HIDDEN + c * 8);
        }
    };

    issue(0, 0); CP_COMMIT();
    issue(1, 1); CP_COMMIT();

    for (int i = 0; i < NSTG_G; i++) {
        CP_WAIT1();
        __syncthreads();
        if (i + 2 < NSTG_G) issue(i + 2, (i + 2) % 3);
        CP_COMMIT();

        const unsigned aB = aFrag + (i % 3) * GST_ST;
        const unsigned bB = bFrag + (i % 3) * GST_ST;
#pragma unroll
        for (int ks = 0; ks < 2; ks++) {
            unsigned bb[4][4];
#pragma unroll
            for (int jt = 0; jt < 4; jt++)
                ldsm4(bb[jt][0], bb[jt][1], bb[jt][2], bb[jt][3],
                      bB + jt * 16 * GROWB + ks * 32);
#pragma unroll
            for (int mt = 0; mt < 4; mt++) {
                unsigned a0, a1, a2, a3;
                ldsm4(a0, a1, a2, a3, aB + mt * 16 * GROWB + ks * 32);
#pragma unroll
                for (int jt = 0; jt < 4; jt++) {
                    mma_fp16(acc[mt][2 * jt],     a0, a1, a2, a3, bb[jt][0], bb[jt][1]);
                    mma_fp16(acc[mt][2 * jt + 1], a0, a1, a2, a3, bb[jt][2], bb[jt][3]);
                }
            }
        }
    }

    // Epilogue (identical mapping to round 7)
    if (mode == 0) {
#pragma unroll
        for (int j = 0; j < 8; j++) {
            int o = o0 + warp_n * 64 + j * 8 + 2 * tg;   // even
            float b0f = Bi[o], b1f = Bi[o + 1];
            int which = o >> 10;
            int cc = o & 1023;
            int h = cc >> 6;
            int d = cc & 63;
            float sc = (which == 0) ? 0.125f : 1.f;
            __half* dst = (which == 0) ? g_q : ((which == 1) ? g_k : g_v);
#pragma unroll
            for (int mt = 0; mt < 4; mt++) {
#pragma unroll
                for (int rr = 0; rr < 2; rr++) {
                    int m = m0 + warp_m * 64 + mt * 16 + gid + rr * 8;
                    int bb_ = m >> 12;
                    int n  = m & 4095;
                    float v0 = (acc[mt][j][rr * 2]     + b0f) * sc;
                    float v1 = (acc[mt][j][rr * 2 + 1] + b1f) * sc;
                    *(__half2*)(dst + (((size_t)(bb_ * HEADS + h)) * SEQ + n) * HDIM + d) =
                        __floats2half2_rn(v0, v1);
                }
            }
        }
    } else {
#pragma unroll
        for (int j = 0; j < 8; j++) {
            int o = o0 + warp_n * 64 + j * 8 + 2 * tg;
            float b0f = Bi[o], b1f = Bi[o + 1];
#pragma unroll
            for (int mt = 0; mt < 4; mt++) {
#pragma unroll
                for (int rr = 0; rr < 2; rr++) {
                    int m = m0 + warp_m * 64 + mt * 16 + gid + rr * 8;
                    *(float2*)(OutF + (size_t)m * HIDDEN + o) =
                        make_float2(acc[mt][j][rr * 2] + b0f,
                                    acc[mt][j][rr * 2 + 1] + b1f);
                }
            }
        }
    }
}

// ---------------------------------------------------------------------------
// Flash attention fp16. Q tile 128, KV tile 64, 128 threads = 4 warps (m32).
// 3-stage cp.async KV ring, single __syncthreads per KV tile.
// smem halfs, row stride 72 (144B) -> ldmatrix conflict-free.
// ---------------------------------------------------------------------------
#define FSTR     72
#define QBYTES   (128*FSTR*2)         // 18432
#define KVBYTES  (64*FSTR*2)          // 9216
#define AST_ST   (2*KVBYTES)          // 18432 per stage (K+V)
#define A_DSMEM  (QBYTES + 3*AST_ST)  // 73728
#define NKV      (SEQ/64)             // 64

__global__ __launch_bounds__(128) void flash_attn_fp16()
{
    extern __shared__ __align__(16) char asm_[];
    const unsigned sbase = smem_u32(asm_);

    const int bh = blockIdx.y;
    const int qt = blockIdx.x;
    const int tid  = threadIdx.x;
    const int wid  = tid >> 5;
    const int lane = tid & 31;
    const int gid  = lane >> 2;
    const int tg   = lane & 3;
    const int rowbase = wid * 32;

    const int a_row  = (lane & 7) + ((lane >> 3) & 1) * 8;
    const int a_ksel = (lane >> 4) * 8;
    const int b_row  = (lane & 7) + (lane >> 4) * 8;
    const int b_ksel = ((lane >> 3) & 1) * 8;

    const __half* qb = g_q + ((size_t)bh * SEQ + qt * 128) * HDIM;
    const __half* kb = g_k + (size_t)bh * SEQ * HDIM;
    const __half* vb = g_v + (size_t)bh * SEQ * HDIM;

    // fragment bases
    const unsigned qBase = sbase + (rowbase + a_row) * (FSTR * 2) + a_ksel * 2;
    const unsigned kFrag = sbase + QBYTES + b_row * (FSTR * 2) + b_ksel * 2;
    const unsigned vFrag = sbase + QBYTES + KVBYTES + a_row * (FSTR * 2) + a_ksel * 2;

    auto issue_kv = [&](int kt, int s) {
        unsigned kdst = sbase + QBYTES + s * AST_ST;
        unsigned vdst = kdst + KVBYTES;
        const __half* ks = kb + (size_t)(kt * 64) * HDIM;
        const __half* vs = vb + (size_t)(kt * 64) * HDIM;
#pragma unroll
        for (int l = 0; l < 4; l++) {
            int idx = tid + l * 128;         // 0..511
            int r = idx >> 3, c = idx & 7;
            cpa16(kdst + r * 144 + c * 16, ks + (size_t)r * HDIM + c * 8);
            cpa16(vdst + r * 144 + c * 16, vs + (size_t)r * HDIM + c * 8);
        }
    };

    // Q (1024 chunks) + first KV stage in group 0
#pragma unroll
    for (int l = 0; l < 8; l++) {
        int idx = tid + l * 128;             // 0..1023
        int r = idx >> 3, c = idx & 7;
        cpa16(sbase + r * 144 + c * 16, qb + (size_t)r * HDIM + c * 8);
    }
    issue_kv(0, 0); CP_COMMIT();
    issue_kv(1, 1); CP_COMMIT();

    float oacc[2][8][4];
#pragma unroll
    for (int mt = 0; mt < 2; mt++)
#pragma unroll
        for (int j = 0; j < 8; j++)
#pragma unroll
            for (int r = 0; r < 4; r++) oacc[mt][j][r] = 0.f;
    float mrun[2][2], lrun[2][2];
#pragma unroll
    for (int mt = 0; mt < 2; mt++) {
        mrun[mt][0] = -1e30f; mrun[mt][1] = -1e30f;
        lrun[mt][0] = 0.f;    lrun[mt][1] = 0.f;
    }

    for (int i = 0; i < NKV; i++) {
        CP_WAIT1();
        __syncthreads();
        if (i + 2 < NKV) issue_kv(i + 2, (i + 2) % 3);
        CP_COMMIT();

        const unsigned kBase = kFrag + (i % 3) * AST_ST;
        const unsigned vBase = vFrag + (i % 3) * AST_ST;

        // ---- S = Q @ K^T  (warp m32 x n64, k=64) ----
        float sacc[2][8][4];
#pragma unroll
        for (int mt = 0; mt < 2; mt++)
#pragma unroll
            for (int j = 0; j < 8; j++)
#pragma unroll
                for (int r = 0; r < 4; r++) sacc[mt][j][r] = 0.f;

#pragma unroll
        for (int ks = 0; ks < 4; ks++) {
            unsigned bb[4][4];
#pragma unroll
            for (int jt = 0; jt < 4; jt++)
                ldsm4(bb[jt][0], bb[jt][1], bb[jt][2], bb[jt][3],
                      kBase + (jt * 16 * FSTR + ks * 16) * 2);
#pragma unroll
            for (int mt = 0; mt < 2; mt++) {
                unsigned a0, a1, a2, a3;
                ldsm4(a0, a1, a2, a3, qBase + (mt * 16 * FSTR + ks * 16) * 2);
#pragma unroll
                for (int jt = 0; jt < 4; jt++) {
                    mma_fp16(sacc[mt][2 * jt],     a0, a1, a2, a3, bb[jt][0], bb[jt][1]);
                    mma_fp16(sacc[mt][2 * jt + 1], a0, a1, a2, a3, bb[jt][2], bb[jt][3]);
                }
            }
        }

        // ---- online softmax; P packed into registers ----
        unsigned ph0[2][8], ph1[2][8];
#pragma unroll
        for (int mt = 0; mt < 2; mt++) {
            float mx0 = -1e30f, mx1 = -1e30f;
#pragma unroll
            for (int j = 0; j < 8; j++) {
                mx0 = fmaxf(mx0, fmaxf(sacc[mt][j][0], sacc[mt][j][1]));
                mx1 = fmaxf(mx1, fmaxf(sacc[mt][j][2], sacc[mt][j][3]));
            }
#pragma unroll
            for (int off = 1; off <= 2; off <<= 1) {
                mx0 = fmaxf(mx0, __shfl_xor_sync(0xffffffffu, mx0, off));
                mx1 = fmaxf(mx1, __shfl_xor_sync(0xffffffffu, mx1, off));
            }
            float mn0 = fmaxf(mrun[mt][0], mx0);
            float mn1 = fmaxf(mrun[mt][1], mx1);
            float scl0 = __expf(mrun[mt][0] - mn0);
            float scl1 = __expf(mrun[mt][1] - mn1);
            mrun[mt][0] = mn0; mrun[mt][1] = mn1;

            float sum0 = 0.f, sum1 = 0.f;
#pragma unroll
            for (int j = 0; j < 8; j++) {
                float p00 = __expf(sacc[mt][j][0] - mn0);
                float p01 = __expf(sacc[mt][j][1] - mn0);
                float p10 = __expf(sacc[mt][j][2] - mn1);
                float p11 = __expf(sacc[mt][j][3] - mn1);
                sum0 += p00 + p01;
                sum1 += p10 + p11;
                ph0[mt][j] = pack_h2(p00, p01);
                ph1[mt][j] = pack_h2(p10, p11);
            }
#pragma unroll
            for (int off = 1; off <= 2; off <<= 1) {
                sum0 += __shfl_xor_sync(0xffffffffu, sum0, off);
                sum1 += __shfl_xor_sync(0xffffffffu, sum1, off);
            }
            lrun[mt][0] = lrun[mt][0] * scl0 + sum0;
            lrun[mt][1] = lrun[mt][1] * scl1 + sum1;

#pragma unroll
            for (int j = 0; j < 8; j++) {
                oacc[mt][j][0] *= scl0; oacc[mt][j][1] *= scl0;
                oacc[mt][j][2] *= scl1; oacc[mt][j][3] *= scl1;
            }
        }

        // ---- O += P @ V ----
#pragma unroll
        for (int kb2 = 0; kb2 < 4; kb2++) {
            unsigned vv[4][4];
#pragma unroll
            for (int jt = 0; jt < 4; jt++)
                ldsm4t(vv[jt][0], vv[jt][1], vv[jt][2], vv[jt][3],
                       vBase + (kb2 * 16 * FSTR + jt * 16) * 2);
#pragma unroll
            for (int mt = 0; mt < 2; mt++) {
                unsigned a0 = ph0[mt][2 * kb2];
                unsigned a1 = ph1[mt][2 * kb2];
                unsigned a2 = ph0[mt][2 * kb2 + 1];
                unsigned a3 = ph1[mt][2 * kb2 + 1];
#pragma unroll
                for (int jt = 0; jt < 4; jt++) {
                    mma_fp16(oacc[mt][2 * jt],     a0, a1, a2, a3, vv[jt][0], vv[jt][1]);
                    mma_fp16(oacc[mt][2 * jt + 1], a0, a1, a2, a3, vv[jt][2], vv[jt][3]);
                }
            }
        }
    }

    // Epilogue: normalize, write half2 into g_ao [B,N,C]
    const int b = bh >> 4, h = bh & 15;
#pragma unroll
    for (int mt = 0; mt < 2; mt++) {
        float inv0 = 1.f / lrun[mt][0];
        float inv1 = 1.f / lrun[mt][1];
        int n0 = qt * 128 + rowbase + mt * 16 + gid;
        int n1 = n0 + 8;
#pragma unroll
        for (int j = 0; j < 8; j++) {
            int d = j * 8 + 2 * tg;
            *(__half2*)(g_ao + ((size_t)b * SEQ + n0) * HIDDEN + h * 64 + d) =
                __floats2half2_rn(oacc[mt][j][0] * inv0, oacc[mt][j][1] * inv0);
            *(__half2*)(g_ao + ((size_t)b * SEQ + n1) * HIDDEN + h * 64 + d) =
                __floats2half2_rn(oacc[mt][j][2] * inv1, oacc[mt][j][3] * inv1);
        }
    }
}

// ---------------------------------------------------------------------------
extern "C" void kernel_launch(void* const* d_in, const int* in_sizes, int n_in,
                              void* d_out, int out_size)
{
    const float* x     = (const float*)d_in[0];
    const float* qkv_w = (const float*)d_in[1];
    const float* qkv_b = (const float*)d_in[2];
    const float* out_w = (const float*)d_in[3];
    const float* out_b = (const float*)d_in[4];
    float* out = (float*)d_out;

    cudaFuncSetAttribute(gemm_tc,
                         cudaFuncAttributeMaxDynamicSharedMemorySize, G_DSMEM);
    cudaFuncSetAttribute(flash_attn_fp16,
                         cudaFuncAttributeMaxDynamicSharedMemorySize, A_DSMEM);

    cvt_fp16<<<512, 256>>>(x,     0, M_TOT * HIDDEN);
    cvt_fp16<<<512, 256>>>(qkv_w, 1, QKV_O * HIDDEN);
    cvt_fp16<<<512, 256>>>(out_w, 2, HIDDEN * HIDDEN);

    gemm_tc<<<dim3(QKV_O / 128, M_TOT / 128), 128, G_DSMEM>>>(qkv_b, nullptr, 0);
    flash_attn_fp16<<<dim3(SEQ / 128, BATCH * HEADS), 128, A_DSMEM>>>();
    gemm_tc<<<dim3(HIDDEN / 128, M_TOT / 128), 128, G_DSMEM>>>(out_b, out, 1);
}